// round 6
// baseline (speedup 1.0000x reference)
#include <cuda_runtime.h>

#define N_NODES 100000
#define N_EDGES 1600000
#define C 128
#define NG 128
#define LSLOPE 0.01f

// ---------------- scratch (device globals: no allocation allowed) ----------
__device__ __align__(16) float g_B1[(size_t)N_NODES * C];   // GEMM output H
__device__ __align__(16) float g_B2[(size_t)N_NODES * C];   // AGG / layer input
__device__ int   g_deg_i[N_NODES];
__device__ float g_dinv[N_NODES];
__device__ int   g_off[N_NODES + 1];       // CSR offsets (by dst)
__device__ int   g_cursor[N_NODES];        // fill cursors
__device__ int   g_esrc[N_EDGES];          // src per CSR slot
__device__ float g_enorm[N_EDGES];         // dinv[s]*dinv[d] per CSR slot
__device__ __align__(16) float g_sums[NG * C];
__device__ float g_cnts[NG];

__device__ __forceinline__ float lrelu(float v) { return v > 0.f ? v : LSLOPE * v; }

// ---------------- prep: zero accumulators ----------------------------------
__global__ void zero_prep_kernel() {
    int i = blockIdx.x * blockDim.x + threadIdx.x;
    if (i < N_NODES) g_deg_i[i] = 0;
    if (i < NG * C)  g_sums[i] = 0.f;
    if (i < NG)      g_cnts[i] = 0.f;
}

// ---------------- degree histogram (int) ------------------------------------
__global__ void deg_kernel(const int* __restrict__ ei) {
    int e = blockIdx.x * blockDim.x + threadIdx.x;
    if (e < N_EDGES) {
        unsigned d = (unsigned)ei[N_EDGES + e];
        if (d < N_NODES) atomicAdd(&g_deg_i[d], 1);
    }
}

// ---------------- single-block scan: offsets, cursors, dinv -----------------
__global__ __launch_bounds__(1024)
void scan_kernel() {
    __shared__ int part[1024];
    const int CHUNK = (N_NODES + 1023) / 1024;   // 98
    int t = threadIdx.x;
    int start = t * CHUNK;
    int end = min(start + CHUNK, N_NODES);

    int s = 0;
    for (int i = start; i < end; i++) s += g_deg_i[i];
    part[t] = s;
    __syncthreads();

    for (int off = 1; off < 1024; off <<= 1) {
        int v = (t >= off) ? part[t - off] : 0;
        __syncthreads();
        part[t] += v;
        __syncthreads();
    }

    int running = part[t] - s;   // exclusive base for this chunk
    for (int i = start; i < end; i++) {
        g_off[i] = running;
        g_cursor[i] = running;
        int d = g_deg_i[i];
        running += d;
        g_dinv[i] = rsqrtf((float)d + 1.0f);
    }
    if (t == 1023) g_off[N_NODES] = running;
}

// ---------------- CSR fill: permute edges by dst -----------------------------
__global__ void fill_kernel(const int* __restrict__ ei) {
    int e = blockIdx.x * blockDim.x + threadIdx.x;
    if (e >= N_EDGES) return;
    unsigned s = (unsigned)ei[e];
    unsigned d = (unsigned)ei[N_EDGES + e];
    if (s >= N_NODES || d >= N_NODES) return;
    int pos = atomicAdd(&g_cursor[d], 1);
    g_esrc[pos]  = (int)s;
    g_enorm[pos] = g_dinv[s] * g_dinv[d];
}

// ---------------- fused GEMM: H = act(X) @ W ; AGG = H * dinv^2 ------------
// 128x128 tile, 256 threads, 8x8 per thread. Tail rows handled by clamp+guard.
template <bool TRANSFORM>
__global__ __launch_bounds__(256)
void gemm_kernel(const float* __restrict__ Xext, const float* __restrict__ W,
                 const float* __restrict__ bin)
{
    __shared__ float  Xs[128][33];
    __shared__ float4 Ws4[32][32];   // [kk][col/4]

    const float* __restrict__ X = TRANSFORM ? (const float*)g_B2 : Xext;

    int tid  = threadIdx.x;
    int row0 = blockIdx.x * 128;
    int tx   = tid & 15;     // col group: cols tx*8 .. tx*8+7
    int ty   = tid >> 4;     // row group: rows ty*8 .. ty*8+7

    float acc[8][8];
#pragma unroll
    for (int i = 0; i < 8; i++)
#pragma unroll
        for (int j = 0; j < 8; j++) acc[i][j] = 0.f;

    for (int kt = 0; kt < 4; ++kt) {
        // load X tile 128x32 (4 float4 per thread), clamped at tail
#pragma unroll
        for (int t = 0; t < 4; t++) {
            int idx = tid + t * 256;         // 0..1023
            int r   = idx >> 3;              // 0..127
            int c   = (idx & 7) * 4;         // 0..28
            int kcol = kt * 32 + c;
            int grow = min(row0 + r, N_NODES - 1);
            float4 v = *(const float4*)(X + (size_t)grow * C + kcol);
            if (TRANSFORM) {
                v.x = lrelu(v.x + bin[kcol + 0]);
                v.y = lrelu(v.y + bin[kcol + 1]);
                v.z = lrelu(v.z + bin[kcol + 2]);
                v.w = lrelu(v.w + bin[kcol + 3]);
            }
            Xs[r][c + 0] = v.x; Xs[r][c + 1] = v.y;
            Xs[r][c + 2] = v.z; Xs[r][c + 3] = v.w;
        }
        // load W tile 32x128 (4 float4 per thread)
#pragma unroll
        for (int t = 0; t < 4; t++) {
            int idx = tid + t * 256;
            int kk  = idx >> 5;
            int c4  = idx & 31;
            Ws4[kk][c4] = *(const float4*)(W + (size_t)(kt * 32 + kk) * C + c4 * 4);
        }
        __syncthreads();

#pragma unroll
        for (int kk = 0; kk < 32; ++kk) {
            float xr[8];
#pragma unroll
            for (int i = 0; i < 8; i++) xr[i] = Xs[ty * 8 + i][kk];
            float4 wa = Ws4[kk][tx * 2 + 0];
            float4 wb = Ws4[kk][tx * 2 + 1];
#pragma unroll
            for (int i = 0; i < 8; i++) {
                acc[i][0] += xr[i] * wa.x; acc[i][1] += xr[i] * wa.y;
                acc[i][2] += xr[i] * wa.z; acc[i][3] += xr[i] * wa.w;
                acc[i][4] += xr[i] * wb.x; acc[i][5] += xr[i] * wb.y;
                acc[i][6] += xr[i] * wb.z; acc[i][7] += xr[i] * wb.w;
            }
        }
        __syncthreads();
    }

    // epilogue: H -> g_B1, AGG = H * dinv^2 -> g_B2 (guarded at tail)
#pragma unroll
    for (int i = 0; i < 8; i++) {
        int r = row0 + ty * 8 + i;
        if (r >= N_NODES) break;
        float d  = g_dinv[r];
        float d2 = d * d;
        float4 h0 = make_float4(acc[i][0], acc[i][1], acc[i][2], acc[i][3]);
        float4 h1 = make_float4(acc[i][4], acc[i][5], acc[i][6], acc[i][7]);
        size_t base = (size_t)r * C + tx * 8;
        *(float4*)(g_B1 + base + 0) = h0;
        *(float4*)(g_B1 + base + 4) = h1;
        float4 a0 = make_float4(h0.x * d2, h0.y * d2, h0.z * d2, h0.w * d2);
        float4 a1 = make_float4(h1.x * d2, h1.y * d2, h1.z * d2, h1.w * d2);
        *(float4*)(g_B2 + base + 0) = a0;
        *(float4*)(g_B2 + base + 4) = a1;
    }
}

// ---------------- aggregation: warp per dst node, unroll-4 -------------------
__global__ __launch_bounds__(256)
void agg_kernel()
{
    int node = (blockIdx.x * blockDim.x + threadIdx.x) >> 5;
    int lane = threadIdx.x & 31;
    if (node >= N_NODES) return;

    int beg = g_off[node];
    int end = g_off[node + 1];

    float4 a0 = make_float4(0.f, 0.f, 0.f, 0.f);
    float4 a1 = make_float4(0.f, 0.f, 0.f, 0.f);
    float4 a2 = make_float4(0.f, 0.f, 0.f, 0.f);
    float4 a3 = make_float4(0.f, 0.f, 0.f, 0.f);

    int i = beg;
    for (; i + 4 <= end; i += 4) {
        int   s0 = g_esrc[i + 0];
        int   s1 = g_esrc[i + 1];
        int   s2 = g_esrc[i + 2];
        int   s3 = g_esrc[i + 3];
        float n0 = g_enorm[i + 0];
        float n1 = g_enorm[i + 1];
        float n2 = g_enorm[i + 2];
        float n3 = g_enorm[i + 3];
        float4 v0 = *(const float4*)(g_B1 + (size_t)s0 * C + lane * 4);
        float4 v1 = *(const float4*)(g_B1 + (size_t)s1 * C + lane * 4);
        float4 v2 = *(const float4*)(g_B1 + (size_t)s2 * C + lane * 4);
        float4 v3 = *(const float4*)(g_B1 + (size_t)s3 * C + lane * 4);
        a0.x += v0.x * n0; a0.y += v0.y * n0; a0.z += v0.z * n0; a0.w += v0.w * n0;
        a1.x += v1.x * n1; a1.y += v1.y * n1; a1.z += v1.z * n1; a1.w += v1.w * n1;
        a2.x += v2.x * n2; a2.y += v2.y * n2; a2.z += v2.z * n2; a2.w += v2.w * n2;
        a3.x += v3.x * n3; a3.y += v3.y * n3; a3.z += v3.z * n3; a3.w += v3.w * n3;
    }
    for (; i < end; i++) {
        int   s0 = g_esrc[i];
        float n0 = g_enorm[i];
        float4 v0 = *(const float4*)(g_B1 + (size_t)s0 * C + lane * 4);
        a0.x += v0.x * n0; a0.y += v0.y * n0; a0.z += v0.z * n0; a0.w += v0.w * n0;
    }

    float* p = g_B2 + (size_t)node * C + lane * 4;   // holds self-loop term
    float4 cur = *(const float4*)p;
    cur.x += (a0.x + a1.x) + (a2.x + a3.x);
    cur.y += (a0.y + a1.y) + (a2.y + a3.y);
    cur.z += (a0.z + a1.z) + (a2.z + a3.z);
    cur.w += (a0.w + a1.w) + (a2.w + a3.w);
    *(float4*)p = cur;
}

// ---------------- pool: sums[g] += lrelu(AGG + b2); cnts[g] += 1 ------------
__global__ __launch_bounds__(256)
void pool_kernel(const int* __restrict__ batch, const float* __restrict__ b2)
{
    int node = (blockIdx.x * blockDim.x + threadIdx.x) >> 5;
    int lane = threadIdx.x & 31;
    if (node >= N_NODES) return;
    unsigned g = (unsigned)batch[node];
    if (g >= NG) return;
    float4 v = *(const float4*)(g_B2 + (size_t)node * C + lane * 4);
    float4 b = *(const float4*)(b2 + lane * 4);
    v.x = lrelu(v.x + b.x); v.y = lrelu(v.y + b.y);
    v.z = lrelu(v.z + b.z); v.w = lrelu(v.w + b.w);
    float* p = g_sums + g * C + lane * 4;
    atomicAdd(p + 0, v.x);
    atomicAdd(p + 1, v.y);
    atomicAdd(p + 2, v.z);
    atomicAdd(p + 3, v.w);
    if (lane == 0) atomicAdd(&g_cnts[g], 1.0f);
}

// ---------------- MLP head ---------------------------------------------------
__global__ __launch_bounds__(128)
void head_kernel(const float* __restrict__ W3, const float* __restrict__ b3,
                 const float* __restrict__ W4, const float* __restrict__ b4,
                 const float* __restrict__ W5, const float* __restrict__ b5,
                 float* __restrict__ out)
{
    int g = blockIdx.x;
    int t = threadIdx.x;
    __shared__ float gv[128], t1[64], t2[64];

    float inv = 1.0f / fmaxf(g_cnts[g], 1.0f);
    gv[t] = g_sums[g * C + t] * inv;
    __syncthreads();

    if (t < 64) {
        float s = b3[t];
#pragma unroll 8
        for (int k = 0; k < 128; k++) s += gv[k] * W3[k * 64 + t];
        t1[t] = lrelu(s);
    }
    __syncthreads();
    if (t < 64) {
        float s = b4[t];
#pragma unroll 8
        for (int k = 0; k < 64; k++) s += t1[k] * W4[k * 64 + t];
        t2[t] = lrelu(s);
    }
    __syncthreads();
    if (t < 10) {
        float s = b5[t];
#pragma unroll 8
        for (int k = 0; k < 64; k++) s += t2[k] * W5[k * 10 + t];
        out[g * 10 + t] = s;
    }
}

// ---------------- launch ----------------------------------------------------
// Inputs resolved by ELEMENT COUNT (ordering-agnostic). edge_index/batch are
// int32 (JAX x64 disabled downcasts int64 -> int32).
extern "C" void kernel_launch(void* const* d_in, const int* in_sizes, int n_in,
                              void* d_out, int out_size)
{
    const float* x = nullptr;
    const int* ei = nullptr;
    const int* batch = nullptr;
    const float *W1 = nullptr, *b1 = nullptr, *W2 = nullptr, *b2 = nullptr;
    const float *W3 = nullptr, *b3 = nullptr, *W4 = nullptr, *b4 = nullptr;
    const float *W5 = nullptr, *b5 = nullptr;

    for (int i = 0; i < n_in; i++) {
        const void* p = d_in[i];
        switch (in_sizes[i]) {
            case 12800000: x = (const float*)p; break;
            case 3200000:  ei = (const int*)p; break;
            case 100000:   batch = (const int*)p; break;
            case 16384:    if (!W1) W1 = (const float*)p; else W2 = (const float*)p; break;
            case 8192:     W3 = (const float*)p; break;
            case 4096:     W4 = (const float*)p; break;
            case 640:      W5 = (const float*)p; break;
            case 128:      if (!b1) b1 = (const float*)p; else b2 = (const float*)p; break;
            case 64:       if (!b3) b3 = (const float*)p; else b4 = (const float*)p; break;
            case 10:       b5 = (const float*)p; break;
            default: break;
        }
    }
    float* out = (float*)d_out;
    (void)out_size;

    const int GEMM_GRID = (N_NODES + 127) / 128;   // 782

    // CSR build (once, reused by both layers)
    zero_prep_kernel<<<(N_NODES + 255) / 256, 256>>>();
    deg_kernel<<<(N_EDGES + 255) / 256, 256>>>(ei);
    scan_kernel<<<1, 1024>>>();
    fill_kernel<<<(N_EDGES + 255) / 256, 256>>>(ei);

    // layer 1
    gemm_kernel<false><<<GEMM_GRID, 256>>>(x, W1, nullptr);
    agg_kernel<<<(N_NODES * 32 + 255) / 256, 256>>>();

    // layer 2
    gemm_kernel<true><<<GEMM_GRID, 256>>>(nullptr, W2, b1);
    agg_kernel<<<(N_NODES * 32 + 255) / 256, 256>>>();

    // pool + head
    pool_kernel<<<(N_NODES * 32 + 255) / 256, 256>>>(batch, b2);
    head_kernel<<<NG, 128>>>(W3, b3, W4, b4, W5, b5, out);
}

// round 7
// speedup vs baseline: 1.0250x; 1.0250x over previous
#include <cuda_runtime.h>

#define N_NODES 100000
#define N_EDGES 1600000
#define C 128
#define NG 128
#define LSLOPE 0.01f
#define FULL 0xffffffffu

// ---------------- scratch (device globals: no allocation allowed) ----------
__device__ __align__(16) float g_B1[(size_t)N_NODES * C];   // GEMM output H
__device__ __align__(16) float g_B2[(size_t)N_NODES * C];   // AGG / layer input
__device__ int   g_deg_i[N_NODES];
__device__ float g_dinv[N_NODES];
__device__ int   g_off[N_NODES + 1];       // CSR offsets (by dst)
__device__ int   g_cursor[N_NODES];        // fill cursors
__device__ int   g_esrc[N_EDGES];          // src per CSR slot
__device__ float g_enorm[N_EDGES];         // dinv[s]*dinv[d] per CSR slot
__device__ __align__(16) float g_sums[NG * C];
__device__ float g_cnts[NG];

__device__ __forceinline__ float lrelu(float v) { return v > 0.f ? v : LSLOPE * v; }

// ---------------- prep: zero accumulators ----------------------------------
__global__ void zero_prep_kernel() {
    int i = blockIdx.x * blockDim.x + threadIdx.x;
    if (i < N_NODES) g_deg_i[i] = 0;
    if (i < NG * C)  g_sums[i] = 0.f;
    if (i < NG)      g_cnts[i] = 0.f;
}

// ---------------- degree histogram (int) ------------------------------------
__global__ void deg_kernel(const int* __restrict__ ei) {
    int e = blockIdx.x * blockDim.x + threadIdx.x;
    if (e < N_EDGES) {
        unsigned d = (unsigned)ei[N_EDGES + e];
        if (d < N_NODES) atomicAdd(&g_deg_i[d], 1);
    }
}

// ---------------- single-block scan: offsets, cursors, dinv -----------------
__global__ __launch_bounds__(1024)
void scan_kernel() {
    __shared__ int part[1024];
    const int CHUNK = (N_NODES + 1023) / 1024;   // 98
    int t = threadIdx.x;
    int start = t * CHUNK;
    int end = min(start + CHUNK, N_NODES);

    int s = 0;
    for (int i = start; i < end; i++) s += g_deg_i[i];
    part[t] = s;
    __syncthreads();

    for (int off = 1; off < 1024; off <<= 1) {
        int v = (t >= off) ? part[t - off] : 0;
        __syncthreads();
        part[t] += v;
        __syncthreads();
    }

    int running = part[t] - s;   // exclusive base for this chunk
    for (int i = start; i < end; i++) {
        g_off[i] = running;
        g_cursor[i] = running;
        int d = g_deg_i[i];
        running += d;
        g_dinv[i] = rsqrtf((float)d + 1.0f);
    }
    if (t == 1023) g_off[N_NODES] = running;
}

// ---------------- CSR fill: permute edges by dst -----------------------------
__global__ void fill_kernel(const int* __restrict__ ei) {
    int e = blockIdx.x * blockDim.x + threadIdx.x;
    if (e >= N_EDGES) return;
    unsigned s = (unsigned)ei[e];
    unsigned d = (unsigned)ei[N_EDGES + e];
    if (s >= N_NODES || d >= N_NODES) return;
    int pos = atomicAdd(&g_cursor[d], 1);
    g_esrc[pos]  = (int)s;
    g_enorm[pos] = g_dinv[s] * g_dinv[d];
}

// ---------------- fused GEMM (R5 version): H = act(X)@W ; AGG = H*dinv^2 ----
template <bool TRANSFORM>
__global__ __launch_bounds__(256)
void gemm_kernel(const float* __restrict__ Xext, const float* __restrict__ W,
                 const float* __restrict__ bin)
{
    __shared__ float  Xs[32][33];
    __shared__ float4 Ws4[32][32];   // [kk][col/4]

    const float* __restrict__ X = TRANSFORM ? (const float*)g_B2 : Xext;

    int tid  = threadIdx.x;
    int row0 = blockIdx.x * 32;
    int tx   = tid & 31;
    int ty   = tid >> 5;

    float acc[4][4];
#pragma unroll
    for (int i = 0; i < 4; i++)
#pragma unroll
        for (int j = 0; j < 4; j++) acc[i][j] = 0.f;

    for (int kt = 0; kt < 4; ++kt) {
        {
            int r = tid >> 3;
            int c = (tid & 7) * 4;
            int kcol = kt * 32 + c;
            float4 v = *(const float4*)(X + (size_t)(row0 + r) * C + kcol);
            if (TRANSFORM) {
                v.x = lrelu(v.x + bin[kcol + 0]);
                v.y = lrelu(v.y + bin[kcol + 1]);
                v.z = lrelu(v.z + bin[kcol + 2]);
                v.w = lrelu(v.w + bin[kcol + 3]);
            }
            Xs[r][c + 0] = v.x; Xs[r][c + 1] = v.y;
            Xs[r][c + 2] = v.z; Xs[r][c + 3] = v.w;
        }
#pragma unroll
        for (int i = 0; i < 4; i++) {
            int idx = tid + i * 256;
            int kk  = idx >> 5;
            int c4  = idx & 31;
            Ws4[kk][c4] = *(const float4*)(W + (size_t)(kt * 32 + kk) * C + c4 * 4);
        }
        __syncthreads();

#pragma unroll
        for (int kk = 0; kk < 32; ++kk) {
            float x0 = Xs[ty * 4 + 0][kk];
            float x1 = Xs[ty * 4 + 1][kk];
            float x2 = Xs[ty * 4 + 2][kk];
            float x3 = Xs[ty * 4 + 3][kk];
            float4 w = Ws4[kk][tx];
            acc[0][0] += x0 * w.x; acc[0][1] += x0 * w.y; acc[0][2] += x0 * w.z; acc[0][3] += x0 * w.w;
            acc[1][0] += x1 * w.x; acc[1][1] += x1 * w.y; acc[1][2] += x1 * w.z; acc[1][3] += x1 * w.w;
            acc[2][0] += x2 * w.x; acc[2][1] += x2 * w.y; acc[2][2] += x2 * w.z; acc[2][3] += x2 * w.w;
            acc[3][0] += x3 * w.x; acc[3][1] += x3 * w.y; acc[3][2] += x3 * w.z; acc[3][3] += x3 * w.w;
        }
        __syncthreads();
    }

#pragma unroll
    for (int i = 0; i < 4; i++) {
        int r = row0 + ty * 4 + i;
        float d  = g_dinv[r];
        float d2 = d * d;
        float4 h = make_float4(acc[i][0], acc[i][1], acc[i][2], acc[i][3]);
        *(float4*)(g_B1 + (size_t)r * C + tx * 4) = h;
        float4 a = make_float4(h.x * d2, h.y * d2, h.z * d2, h.w * d2);
        *(float4*)(g_B2 + (size_t)r * C + tx * 4) = a;
    }
}

// ---------------- aggregation v3: coalesced index load + shuffle broadcast --
// Warp per dst node. Lanes cooperatively load 32 edge (src, norm) pairs in ONE
// coalesced pass, then broadcast via shfl so row gathers issue back-to-back
// (no per-edge index-load latency in the dependency chain).
__global__ __launch_bounds__(256)
void agg_kernel()
{
    int node = (blockIdx.x * blockDim.x + threadIdx.x) >> 5;
    int lane = threadIdx.x & 31;
    if (node >= N_NODES) return;

    int beg = g_off[node];
    int end = g_off[node + 1];

    float4 a0 = make_float4(0.f, 0.f, 0.f, 0.f);
    float4 a1 = make_float4(0.f, 0.f, 0.f, 0.f);
    float4 a2 = make_float4(0.f, 0.f, 0.f, 0.f);
    float4 a3 = make_float4(0.f, 0.f, 0.f, 0.f);

    for (int chunk = beg; chunk < end; chunk += 32) {
        int i = chunk + lane;
        int   sl = 0;
        float nl = 0.f;
        if (i < end) { sl = g_esrc[i]; nl = g_enorm[i]; }
        int cnt = min(32, end - chunk);

        int j = 0;
        for (; j + 4 <= cnt; j += 4) {
            int   s0 = __shfl_sync(FULL, sl, j + 0);
            int   s1 = __shfl_sync(FULL, sl, j + 1);
            int   s2 = __shfl_sync(FULL, sl, j + 2);
            int   s3 = __shfl_sync(FULL, sl, j + 3);
            float n0 = __shfl_sync(FULL, nl, j + 0);
            float n1 = __shfl_sync(FULL, nl, j + 1);
            float n2 = __shfl_sync(FULL, nl, j + 2);
            float n3 = __shfl_sync(FULL, nl, j + 3);
            float4 v0 = *(const float4*)(g_B1 + (size_t)s0 * C + lane * 4);
            float4 v1 = *(const float4*)(g_B1 + (size_t)s1 * C + lane * 4);
            float4 v2 = *(const float4*)(g_B1 + (size_t)s2 * C + lane * 4);
            float4 v3 = *(const float4*)(g_B1 + (size_t)s3 * C + lane * 4);
            a0.x += v0.x * n0; a0.y += v0.y * n0; a0.z += v0.z * n0; a0.w += v0.w * n0;
            a1.x += v1.x * n1; a1.y += v1.y * n1; a1.z += v1.z * n1; a1.w += v1.w * n1;
            a2.x += v2.x * n2; a2.y += v2.y * n2; a2.z += v2.z * n2; a2.w += v2.w * n2;
            a3.x += v3.x * n3; a3.y += v3.y * n3; a3.z += v3.z * n3; a3.w += v3.w * n3;
        }
        for (; j < cnt; j++) {
            int   s0 = __shfl_sync(FULL, sl, j);
            float n0 = __shfl_sync(FULL, nl, j);
            float4 v0 = *(const float4*)(g_B1 + (size_t)s0 * C + lane * 4);
            a0.x += v0.x * n0; a0.y += v0.y * n0; a0.z += v0.z * n0; a0.w += v0.w * n0;
        }
    }

    float* p = g_B2 + (size_t)node * C + lane * 4;   // holds self-loop term
    float4 cur = *(const float4*)p;
    cur.x += (a0.x + a1.x) + (a2.x + a3.x);
    cur.y += (a0.y + a1.y) + (a2.y + a3.y);
    cur.z += (a0.z + a1.z) + (a2.z + a3.z);
    cur.w += (a0.w + a1.w) + (a2.w + a3.w);
    *(float4*)p = cur;
}

// ---------------- pool: sums[g] += lrelu(AGG + b2); cnts[g] += 1 ------------
__global__ __launch_bounds__(256)
void pool_kernel(const int* __restrict__ batch, const float* __restrict__ b2)
{
    int node = (blockIdx.x * blockDim.x + threadIdx.x) >> 5;
    int lane = threadIdx.x & 31;
    if (node >= N_NODES) return;
    unsigned g = (unsigned)batch[node];
    if (g >= NG) return;
    float4 v = *(const float4*)(g_B2 + (size_t)node * C + lane * 4);
    float4 b = *(const float4*)(b2 + lane * 4);
    v.x = lrelu(v.x + b.x); v.y = lrelu(v.y + b.y);
    v.z = lrelu(v.z + b.z); v.w = lrelu(v.w + b.w);
    float* p = g_sums + g * C + lane * 4;
    atomicAdd(p + 0, v.x);
    atomicAdd(p + 1, v.y);
    atomicAdd(p + 2, v.z);
    atomicAdd(p + 3, v.w);
    if (lane == 0) atomicAdd(&g_cnts[g], 1.0f);
}

// ---------------- MLP head ---------------------------------------------------
__global__ __launch_bounds__(128)
void head_kernel(const float* __restrict__ W3, const float* __restrict__ b3,
                 const float* __restrict__ W4, const float* __restrict__ b4,
                 const float* __restrict__ W5, const float* __restrict__ b5,
                 float* __restrict__ out)
{
    int g = blockIdx.x;
    int t = threadIdx.x;
    __shared__ float gv[128], t1[64], t2[64];

    float inv = 1.0f / fmaxf(g_cnts[g], 1.0f);
    gv[t] = g_sums[g * C + t] * inv;
    __syncthreads();

    if (t < 64) {
        float s = b3[t];
#pragma unroll 8
        for (int k = 0; k < 128; k++) s += gv[k] * W3[k * 64 + t];
        t1[t] = lrelu(s);
    }
    __syncthreads();
    if (t < 64) {
        float s = b4[t];
#pragma unroll 8
        for (int k = 0; k < 64; k++) s += t1[k] * W4[k * 64 + t];
        t2[t] = lrelu(s);
    }
    __syncthreads();
    if (t < 10) {
        float s = b5[t];
#pragma unroll 8
        for (int k = 0; k < 64; k++) s += t2[k] * W5[k * 10 + t];
        out[g * 10 + t] = s;
    }
}

// ---------------- launch ----------------------------------------------------
// Inputs resolved by ELEMENT COUNT (ordering-agnostic). edge_index/batch are
// int32 (JAX x64 disabled downcasts int64 -> int32).
extern "C" void kernel_launch(void* const* d_in, const int* in_sizes, int n_in,
                              void* d_out, int out_size)
{
    const float* x = nullptr;
    const int* ei = nullptr;
    const int* batch = nullptr;
    const float *W1 = nullptr, *b1 = nullptr, *W2 = nullptr, *b2 = nullptr;
    const float *W3 = nullptr, *b3 = nullptr, *W4 = nullptr, *b4 = nullptr;
    const float *W5 = nullptr, *b5 = nullptr;

    for (int i = 0; i < n_in; i++) {
        const void* p = d_in[i];
        switch (in_sizes[i]) {
            case 12800000: x = (const float*)p; break;
            case 3200000:  ei = (const int*)p; break;
            case 100000:   batch = (const int*)p; break;
            case 16384:    if (!W1) W1 = (const float*)p; else W2 = (const float*)p; break;
            case 8192:     W3 = (const float*)p; break;
            case 4096:     W4 = (const float*)p; break;
            case 640:      W5 = (const float*)p; break;
            case 128:      if (!b1) b1 = (const float*)p; else b2 = (const float*)p; break;
            case 64:       if (!b3) b3 = (const float*)p; else b4 = (const float*)p; break;
            case 10:       b5 = (const float*)p; break;
            default: break;
        }
    }
    float* out = (float*)d_out;
    (void)out_size;

    // CSR build (once, reused by both layers)
    zero_prep_kernel<<<(N_NODES + 255) / 256, 256>>>();
    deg_kernel<<<(N_EDGES + 255) / 256, 256>>>(ei);
    scan_kernel<<<1, 1024>>>();
    fill_kernel<<<(N_EDGES + 255) / 256, 256>>>(ei);

    // layer 1
    gemm_kernel<false><<<N_NODES / 32, 256>>>(x, W1, nullptr);
    agg_kernel<<<(N_NODES * 32 + 255) / 256, 256>>>();

    // layer 2
    gemm_kernel<true><<<N_NODES / 32, 256>>>(nullptr, W2, b1);
    agg_kernel<<<(N_NODES * 32 + 255) / 256, 256>>>();

    // pool + head
    pool_kernel<<<(N_NODES * 32 + 255) / 256, 256>>>(batch, b2);
    head_kernel<<<NG, 128>>>(W3, b3, W4, b4, W5, b5, out);
}